// round 3
// baseline (speedup 1.0000x reference)
#include <cuda_runtime.h>
#include <math.h>

#define Bb 8
#define Ss 1024
#define Dd 768
#define THETA 0.01f
#define NCTA 128
#define RPC 6

// ------------------------- scratch globals -------------------------
__device__ float g_k[Ss * Bb * Dd];     // [S][B][D]
__device__ float g_v[Ss * Bb * Dd];     // [S][B][D]
__device__ float g_q[Bb * Ss * Dd];     // [B,S,D] flattened rows
__device__ float g_hid[Bb * Ss * Dd];
__device__ float g_alpha[Ss];
__device__ float g_eta[Ss];
__device__ float g_h1x[2][Dd * Bb];     // [e][b] double buffered
__device__ float g_dyx[2][Dd * Bb];
__device__ float g_W1f[Dd * Dd];
__device__ float g_W2f[Dd * Dd];
__device__ float g_b1f[Dd];
__device__ float g_b2f[Dd];
__device__ unsigned g_bar_count;
__device__ unsigned g_bar_gen;

// ------------------------- grid barrier -------------------------
__device__ __forceinline__ void grid_barrier() {
    __syncthreads();
    if (threadIdx.x == 0) {
        __threadfence();
        unsigned g = atomicAdd(&g_bar_gen, 0u);
        __threadfence();
        unsigned old = atomicAdd(&g_bar_count, 1u);
        if (old == (unsigned)(NCTA - 1)) {
            atomicExch(&g_bar_count, 0u);
            __threadfence();
            atomicAdd(&g_bar_gen, 1u);
        } else {
            while (atomicAdd(&g_bar_gen, 0u) == g) { __nanosleep(64); }
        }
        __threadfence();
    }
    __syncthreads();
}

// ------------------------- GEMM: C = act(A * W^T + bias) -------------------------
// A: [8192,768] row-major, W: [768,768] row-major (dot over K=768)
// LAYOUT 0: C[m*768+n]; LAYOUT 1: m=b*1024+s -> C[(s*8+b)*768+n]
template <int ACT, int LAYOUT>
__global__ __launch_bounds__(256) void gemm_kernel(const float* __restrict__ A,
                                                   const float* __restrict__ W,
                                                   const float* __restrict__ bias,
                                                   float* __restrict__ C) {
    __shared__ float As[16][65];
    __shared__ float Ws[16][65];
    const int m0 = blockIdx.x * 64;
    const int n0 = blockIdx.y * 64;
    const int tid = threadIdx.x;
    const int tx = tid & 15;
    const int ty = tid >> 4;
    const int lrow = tid >> 2;
    const int lc4 = (tid & 3) << 2;

    float acc[4][4];
#pragma unroll
    for (int i = 0; i < 4; i++)
#pragma unroll
        for (int j = 0; j < 4; j++) acc[i][j] = 0.f;

    for (int k0 = 0; k0 < Dd; k0 += 16) {
        float4 av = *(const float4*)&A[(size_t)(m0 + lrow) * Dd + k0 + lc4];
        float4 wv = *(const float4*)&W[(size_t)(n0 + lrow) * Dd + k0 + lc4];
        __syncthreads();
        As[lc4 + 0][lrow] = av.x; As[lc4 + 1][lrow] = av.y;
        As[lc4 + 2][lrow] = av.z; As[lc4 + 3][lrow] = av.w;
        Ws[lc4 + 0][lrow] = wv.x; Ws[lc4 + 1][lrow] = wv.y;
        Ws[lc4 + 2][lrow] = wv.z; Ws[lc4 + 3][lrow] = wv.w;
        __syncthreads();
#pragma unroll
        for (int k = 0; k < 16; k++) {
            float ar[4], wr[4];
#pragma unroll
            for (int i = 0; i < 4; i++) ar[i] = As[k][ty * 4 + i];
#pragma unroll
            for (int j = 0; j < 4; j++) wr[j] = Ws[k][tx * 4 + j];
#pragma unroll
            for (int i = 0; i < 4; i++)
#pragma unroll
                for (int j = 0; j < 4; j++) acc[i][j] += ar[i] * wr[j];
        }
    }

#pragma unroll
    for (int i = 0; i < 4; i++) {
        int m = m0 + ty * 4 + i;
        size_t orow;
        if (LAYOUT == 0) {
            orow = (size_t)m * Dd;
        } else {
            int b = m >> 10;
            int s = m & 1023;
            orow = ((size_t)(s << 3) + b) * Dd;
        }
#pragma unroll
        for (int j = 0; j < 4; j++) {
            int n = n0 + tx * 4 + j;
            float v = acc[i][j] + bias[n];
            if (ACT) v = v / (1.f + expf(-v));
            C[orow + n] = v;
        }
    }
}

// ------------------------- gates: alpha[s], eta[s] -------------------------
__global__ __launch_bounds__(256) void gates_kernel(const float* __restrict__ x,
    const float* __restrict__ FW1, const float* __restrict__ Fb1,
    const float* __restrict__ Fw2, const float* __restrict__ Fb2,
    const float* __restrict__ DW1, const float* __restrict__ Db1,
    const float* __restrict__ Dw2, const float* __restrict__ Db2,
    float* __restrict__ out_alpha, float* __restrict__ out_eta) {
    __shared__ float sx[8][768];
    __shared__ float swF[32][65];
    __shared__ float swD[32][65];
    __shared__ float sred[2][8][32];
    __shared__ float spart[2][8];
    const int s = blockIdx.x;
    const int tid = threadIdx.x;
    const int b = tid >> 5;
    const int g = tid & 31;

    for (int i = tid; i < 6144; i += 256) {
        int bb = i / 768, e = i - bb * 768;
        sx[bb][e] = x[((size_t)bb * 1024 + s) * 768 + e];
    }
    float aF = 0.f, aD = 0.f;
    for (int k0 = 0; k0 < 768; k0 += 64) {
        __syncthreads();
        for (int i = tid; i < 2048; i += 256) {
            int rr = i >> 6, cc = i & 63;
            swF[rr][cc] = FW1[rr * 768 + k0 + cc];
            swD[rr][cc] = DW1[rr * 768 + k0 + cc];
        }
        __syncthreads();
#pragma unroll 8
        for (int kk = 0; kk < 64; kk++) {
            float xv = sx[b][k0 + kk];
            aF += swF[g][kk] * xv;
            aD += swD[g][kk] * xv;
        }
    }
    aF += Fb1[g];
    aD += Db1[g];
    float hF = aF / (1.f + expf(-aF));
    float hD = aD / (1.f + expf(-aD));
    sred[0][b][g] = Fw2[g] * hF;
    sred[1][b][g] = Dw2[g] * hD;
    __syncthreads();
    if (tid < 16) {
        int which = tid >> 3, bb = tid & 7;
        float acc = which ? Db2[0] : Fb2[0];
#pragma unroll
        for (int gg = 0; gg < 32; gg++) acc += sred[which][bb][gg];
        spart[which][bb] = 1.f / (1.f + expf(-acc));
    }
    __syncthreads();
    if (tid == 0) {
        float m = 0.f;
#pragma unroll
        for (int bb = 0; bb < 8; bb++) m += spart[0][bb];
        out_alpha[s] = m * 0.125f;
    }
    if (tid == 1) {
        float m = 0.f;
#pragma unroll
        for (int bb = 0; bb < 8; bb++) m += spart[1][bb];
        out_eta[s] = m * 0.125f;
    }
}

// ------------------------- the sequential scan -------------------------
// 128 CTAs, each owns 6 rows of W1,S1,W2,S2 and 6 "rows" (=columns) of W2T,S2T.
#define SCAN_SMEM_FLOATS (6 * 4608 + 3 * 6912 + 4 * 48 + 24)

__device__ __forceinline__ float warp_reduce(float v) {
    v += __shfl_xor_sync(0xffffffffu, v, 16);
    v += __shfl_xor_sync(0xffffffffu, v, 8);
    v += __shfl_xor_sync(0xffffffffu, v, 4);
    v += __shfl_xor_sync(0xffffffffu, v, 2);
    v += __shfl_xor_sync(0xffffffffu, v, 1);
    return v;
}

__global__ __launch_bounds__(256, 1) void scan_kernel(const float* __restrict__ MW1,
                                                      const float* __restrict__ Mb1,
                                                      const float* __restrict__ MW2,
                                                      const float* __restrict__ Mb2) {
    extern __shared__ float sm[];
    float* sW1  = sm;
    float* sS1  = sW1 + 4608;
    float* sW2  = sS1 + 4608;
    float* sS2  = sW2 + 4608;
    float* sW2T = sS2 + 4608;
    float* sS2T = sW2T + 4608;
    float* skt  = sS2T + 4608;  // [768][9]
    float* sh1  = skt + 6912;   // [768][9]
    float* sdy  = sh1 + 6912;   // [768][9]
    float* svt  = sdy + 6912;   // [6][8]
    float* sa1  = svt + 48;     // [6][8]
    float* sda  = sa1 + 48;     // [6][8]
    float* sdys = sda + 48;     // [6][8]
    float* sb1  = sdys + 48;    // [6]
    float* sSb1 = sb1 + 6;
    float* sb2  = sSb1 + 6;
    float* sSb2 = sb2 + 6;

    const int tid = threadIdx.x;
    const int c = blockIdx.x;
    const int r0 = c * RPC;
    const int w = tid >> 5;
    const int l = tid & 31;

    // init state
    for (int i = tid; i < 4608; i += 256) {
        int rj = i / 768, d = i - rj * 768;
        sW1[i] = MW1[(r0 + rj) * 768 + d];
        sW2[i] = MW2[(r0 + rj) * 768 + d];
        sW2T[i] = MW2[d * 768 + r0 + rj];
        sS1[i] = 0.f;
        sS2[i] = 0.f;
        sS2T[i] = 0.f;
    }
    if (tid < 6) {
        sb1[tid] = Mb1[r0 + tid];
        sb2[tid] = Mb2[r0 + tid];
        sSb1[tid] = 0.f;
        sSb2[tid] = 0.f;
    }
    __syncthreads();

    for (int t = 0; t < Ss; t++) {
        const float at = g_alpha[t];
        const float et = g_eta[t];
        const float ia = 1.f - at;
        const int par = t & 1;

        // load kt transposed [e][b], plus vt slice
        const float* kt = g_k + t * 6144;
        for (int i = tid; i < 6144; i += 256) {
            int b = i / 768, e = i - b * 768;
            skt[e * 9 + b] = kt[i];
        }
        if (tid < 48) {
            int rj = tid >> 3, b = tid & 7;
            svt[tid] = g_v[t * 6144 + b * 768 + r0 + rj];
        }
        __syncthreads();

        // ---- P1: a1/h1 for owned rows (warp w handles batch b=w) ----
        {
            float kv[24];
#pragma unroll
            for (int i = 0; i < 24; i++) kv[i] = skt[(l + 32 * i) * 9 + w];
#pragma unroll
            for (int rj = 0; rj < 6; rj++) {
                const float* wr = sW1 + rj * 768;
                float acc = 0.f;
#pragma unroll
                for (int i = 0; i < 24; i++) acc += wr[l + 32 * i] * kv[i];
                acc = warp_reduce(acc);
                if (l == 0) {
                    float a1 = acc + sb1[rj];
                    sa1[rj * 8 + w] = a1;
                    float h = a1 / (1.f + expf(-a1));
                    g_h1x[par][(r0 + rj) * 8 + w] = h;
                }
            }
        }
        grid_barrier();

        // ---- P2: y/dy for owned rows ----
        for (int i = tid; i < 6144; i += 256) {
            int e = i >> 3, b = i & 7;
            sh1[e * 9 + b] = __ldcg(&g_h1x[par][i]);
        }
        __syncthreads();
        {
            float hv[24];
#pragma unroll
            for (int i = 0; i < 24; i++) hv[i] = sh1[(l + 32 * i) * 9 + w];
#pragma unroll
            for (int rj = 0; rj < 6; rj++) {
                const float* wr = sW2 + rj * 768;
                float acc = 0.f;
#pragma unroll
                for (int i = 0; i < 24; i++) acc += wr[l + 32 * i] * hv[i];
                acc = warp_reduce(acc);
                if (l == 0) {
                    float dy = (acc + sb2[rj] - svt[rj * 8 + w]) * (2.f / 6144.f);
                    sdys[rj * 8 + w] = dy;
                    g_dyx[par][(r0 + rj) * 8 + w] = dy;
                }
            }
        }
        __syncthreads();
        if (tid < 6) {  // b2 update
            float gs = 0.f;
#pragma unroll
            for (int b = 0; b < 8; b++) gs += sdys[tid * 8 + b];
            float s2 = et * sSb2[tid] - THETA * gs;
            sSb2[tid] = s2;
            sb2[tid] = ia * sb2[tid] + s2;
        }
        grid_barrier();

        // ---- P3: dh1/da1 + all weight updates ----
        for (int i = tid; i < 6144; i += 256) {
            int e = i >> 3, b = i & 7;
            sdy[e * 9 + b] = __ldcg(&g_dyx[par][i]);
        }
        __syncthreads();
        {
            float dv[24];
#pragma unroll
            for (int i = 0; i < 24; i++) dv[i] = sdy[(l + 32 * i) * 9 + w];
#pragma unroll
            for (int dj = 0; dj < 6; dj++) {
                const float* wr = sW2T + dj * 768;
                float acc = 0.f;
#pragma unroll
                for (int i = 0; i < 24; i++) acc += wr[l + 32 * i] * dv[i];
                acc = warp_reduce(acc);
                if (l == 0) {
                    float a1 = sa1[dj * 8 + w];
                    float sg = 1.f / (1.f + expf(-a1));
                    float ds = sg * (1.f + a1 * (1.f - sg));
                    sda[dj * 8 + w] = acc * ds;
                }
            }
        }
        __syncthreads();
        if (tid < 6) {  // b1 update
            float gs = 0.f;
#pragma unroll
            for (int b = 0; b < 8; b++) gs += sda[tid * 8 + b];
            float s1 = et * sSb1[tid] - THETA * gs;
            sSb1[tid] = s1;
            sb1[tid] = ia * sb1[tid] + s1;
        }
        // W1/S1 update: g[rj,d] = sum_b da1[rj,b]*kt[d,b]
        {
            float cA[48];
#pragma unroll
            for (int q2 = 0; q2 < 48; q2++) cA[q2] = sda[q2];
            for (int d = tid; d < 768; d += 256) {
                float kv[8];
#pragma unroll
                for (int b = 0; b < 8; b++) kv[b] = skt[d * 9 + b];
#pragma unroll
                for (int rj = 0; rj < 6; rj++) {
                    float gr = 0.f;
#pragma unroll
                    for (int b = 0; b < 8; b++) gr += cA[rj * 8 + b] * kv[b];
                    int idx = rj * 768 + d;
                    float sv = et * sS1[idx] - THETA * gr;
                    sS1[idx] = sv;
                    sW1[idx] = ia * sW1[idx] + sv;
                }
            }
        }
        // W2/S2 rows: g[rj,d] = sum_b dy[rj,b]*h1[d,b]
        {
            float cB[48];
#pragma unroll
            for (int q2 = 0; q2 < 48; q2++) cB[q2] = sdys[q2];
            for (int d = tid; d < 768; d += 256) {
                float hv[8];
#pragma unroll
                for (int b = 0; b < 8; b++) hv[b] = sh1[d * 9 + b];
#pragma unroll
                for (int rj = 0; rj < 6; rj++) {
                    float gr = 0.f;
#pragma unroll
                    for (int b = 0; b < 8; b++) gr += cB[rj * 8 + b] * hv[b];
                    int idx = rj * 768 + d;
                    float sv = et * sS2[idx] - THETA * gr;
                    sS2[idx] = sv;
                    sW2[idx] = ia * sW2[idx] + sv;
                }
            }
        }
        // W2T/S2T rows: g[dj,e] = sum_b dy[e,b]*h1[r0+dj,b]
        {
            float cT[48];
#pragma unroll
            for (int dj = 0; dj < 6; dj++)
#pragma unroll
                for (int b = 0; b < 8; b++) cT[dj * 8 + b] = sh1[(r0 + dj) * 9 + b];
            for (int e = tid; e < 768; e += 256) {
                float dv[8];
#pragma unroll
                for (int b = 0; b < 8; b++) dv[b] = sdy[e * 9 + b];
#pragma unroll
                for (int dj = 0; dj < 6; dj++) {
                    float gr = 0.f;
#pragma unroll
                    for (int b = 0; b < 8; b++) gr += cT[dj * 8 + b] * dv[b];
                    int idx = dj * 768 + e;
                    float sv = et * sS2T[idx] - THETA * gr;
                    sS2T[idx] = sv;
                    sW2T[idx] = ia * sW2T[idx] + sv;
                }
            }
        }
        __syncthreads();
    }

    // write final state
    for (int i = tid; i < 4608; i += 256) {
        int rj = i / 768, d = i - rj * 768;
        g_W1f[(r0 + rj) * 768 + d] = sW1[i];
        g_W2f[(r0 + rj) * 768 + d] = sW2[i];
    }
    if (tid < 6) {
        g_b1f[r0 + tid] = sb1[tid];
        g_b2f[r0 + tid] = sb2[tid];
    }
}

// ------------------------- launch -------------------------
extern "C" void kernel_launch(void* const* d_in, const int* in_sizes, int n_in,
                              void* d_out, int out_size) {
    const float* x   = (const float*)d_in[0];
    const float* WKw = (const float*)d_in[1];
    const float* WKb = (const float*)d_in[2];
    const float* WVw = (const float*)d_in[3];
    const float* WVb = (const float*)d_in[4];
    const float* WQw = (const float*)d_in[5];
    const float* WQb = (const float*)d_in[6];
    const float* MW1 = (const float*)d_in[7];
    const float* Mb1 = (const float*)d_in[8];
    const float* MW2 = (const float*)d_in[9];
    const float* Mb2 = (const float*)d_in[10];
    const float* FW1 = (const float*)d_in[11];
    const float* Fb1 = (const float*)d_in[12];
    const float* Fw2 = (const float*)d_in[13];
    const float* Fb2 = (const float*)d_in[14];
    const float* DW1 = (const float*)d_in[15];
    const float* Db1 = (const float*)d_in[16];
    const float* Dw2 = (const float*)d_in[17];
    const float* Db2 = (const float*)d_in[18];
    float* out = (float*)d_out;

    float *p_k, *p_v, *p_q, *p_hid, *p_alpha, *p_eta, *p_W1f, *p_W2f, *p_b1f, *p_b2f;
    cudaGetSymbolAddress((void**)&p_k, g_k);
    cudaGetSymbolAddress((void**)&p_v, g_v);
    cudaGetSymbolAddress((void**)&p_q, g_q);
    cudaGetSymbolAddress((void**)&p_hid, g_hid);
    cudaGetSymbolAddress((void**)&p_alpha, g_alpha);
    cudaGetSymbolAddress((void**)&p_eta, g_eta);
    cudaGetSymbolAddress((void**)&p_W1f, g_W1f);
    cudaGetSymbolAddress((void**)&p_W2f, g_W2f);
    cudaGetSymbolAddress((void**)&p_b1f, g_b1f);
    cudaGetSymbolAddress((void**)&p_b2f, g_b2f);

    cudaFuncSetAttribute(scan_kernel, cudaFuncAttributeMaxDynamicSharedMemorySize,
                         SCAN_SMEM_FLOATS * 4);

    dim3 gg(128, 12);
    gemm_kernel<0, 1><<<gg, 256>>>(x, WKw, WKb, p_k);
    gemm_kernel<0, 1><<<gg, 256>>>(x, WVw, WVb, p_v);
    gemm_kernel<0, 0><<<gg, 256>>>(x, WQw, WQb, p_q);
    gates_kernel<<<Ss, 256>>>(x, FW1, Fb1, Fw2, Fb2, DW1, Db1, Dw2, Db2, p_alpha, p_eta);
    scan_kernel<<<NCTA, 256, SCAN_SMEM_FLOATS * 4>>>(MW1, Mb1, MW2, Mb2);
    gemm_kernel<1, 0><<<gg, 256>>>(p_q, p_W1f, p_b1f, p_hid);
    gemm_kernel<0, 0><<<gg, 256>>>(p_hid, p_W2f, p_b2f, out);
}

// round 4
// speedup vs baseline: 1.2448x; 1.2448x over previous
#include <cuda_runtime.h>
#include <math.h>

#define Bb 8
#define Ss 1024
#define Dd 768
#define THETA 0.01f
#define NCTA 128
#define RPC 6
#define SCAN_T 384

// ------------------------- scratch globals -------------------------
__device__ float g_k[Ss * Bb * Dd];     // [S][B][D]
__device__ float g_v[Ss * Bb * Dd];     // [S][B][D]
__device__ float g_q[Bb * Ss * Dd];     // [B,S,D] flattened rows
__device__ float g_hid[Bb * Ss * Dd];
__device__ float g_alpha[Ss];
__device__ float g_eta[Ss];
__device__ float g_h1x[2][Dd * Bb];     // [e][b] double buffered
__device__ float g_dyx[2][Dd * Bb];
__device__ float g_W1f[Dd * Dd];
__device__ float g_W2f[Dd * Dd];
__device__ float g_b1f[Dd];
__device__ float g_b2f[Dd];
__device__ unsigned g_bar_count;
__device__ unsigned g_bar_gen;

// ------------------------- grid barrier -------------------------
__device__ __forceinline__ void grid_barrier() {
    __syncthreads();
    if (threadIdx.x == 0) {
        __threadfence();
        volatile unsigned* genp = &g_bar_gen;
        unsigned g = *genp;
        unsigned old = atomicAdd(&g_bar_count, 1u);
        if (old == (unsigned)(NCTA - 1)) {
            atomicExch(&g_bar_count, 0u);
            __threadfence();
            atomicAdd(&g_bar_gen, 1u);
        } else {
            while (*genp == g) { __nanosleep(32); }
        }
        __threadfence();
    }
    __syncthreads();
}

// ------------------------- GEMM: C = act(A * W^T + bias) -------------------------
// A: [8192,768] row-major, W: [768,768] row-major (dot over K=768)
// LAYOUT 0: C[m*768+n]; LAYOUT 1: m=b*1024+s -> C[(s*8+b)*768+n]
template <int ACT, int LAYOUT>
__global__ __launch_bounds__(256) void gemm_kernel(const float* __restrict__ A,
                                                   const float* __restrict__ W,
                                                   const float* __restrict__ bias,
                                                   float* __restrict__ C) {
    __shared__ float As[16][68];
    __shared__ float Ws[16][68];
    const int m0 = blockIdx.x * 64;
    const int n0 = blockIdx.y * 64;
    const int tid = threadIdx.x;
    const int tx = tid & 15;
    const int ty = tid >> 4;
    const int lrow = tid >> 2;
    const int lc4 = (tid & 3) << 2;

    float acc[4][4];
#pragma unroll
    for (int i = 0; i < 4; i++)
#pragma unroll
        for (int j = 0; j < 4; j++) acc[i][j] = 0.f;

    for (int k0 = 0; k0 < Dd; k0 += 16) {
        float4 av = *(const float4*)&A[(size_t)(m0 + lrow) * Dd + k0 + lc4];
        float4 wv = *(const float4*)&W[(size_t)(n0 + lrow) * Dd + k0 + lc4];
        __syncthreads();
        As[lc4 + 0][lrow] = av.x; As[lc4 + 1][lrow] = av.y;
        As[lc4 + 2][lrow] = av.z; As[lc4 + 3][lrow] = av.w;
        Ws[lc4 + 0][lrow] = wv.x; Ws[lc4 + 1][lrow] = wv.y;
        Ws[lc4 + 2][lrow] = wv.z; Ws[lc4 + 3][lrow] = wv.w;
        __syncthreads();
#pragma unroll
        for (int k = 0; k < 16; k++) {
            float4 a4 = *(const float4*)&As[k][ty * 4];
            float4 w4 = *(const float4*)&Ws[k][tx * 4];
            float ar[4] = {a4.x, a4.y, a4.z, a4.w};
            float wr[4] = {w4.x, w4.y, w4.z, w4.w};
#pragma unroll
            for (int i = 0; i < 4; i++)
#pragma unroll
                for (int j = 0; j < 4; j++) acc[i][j] = fmaf(ar[i], wr[j], acc[i][j]);
        }
    }

#pragma unroll
    for (int i = 0; i < 4; i++) {
        int m = m0 + ty * 4 + i;
        size_t orow;
        if (LAYOUT == 0) {
            orow = (size_t)m * Dd;
        } else {
            int b = m >> 10;
            int s = m & 1023;
            orow = ((size_t)(s << 3) + b) * Dd;
        }
#pragma unroll
        for (int j = 0; j < 4; j++) {
            int n = n0 + tx * 4 + j;
            float v = acc[i][j] + bias[n];
            if (ACT) v = v / (1.f + expf(-v));
            C[orow + n] = v;
        }
    }
}

// ------------------------- gates: alpha[s], eta[s] -------------------------
__global__ __launch_bounds__(256) void gates_kernel(const float* __restrict__ x,
    const float* __restrict__ FW1, const float* __restrict__ Fb1,
    const float* __restrict__ Fw2, const float* __restrict__ Fb2,
    const float* __restrict__ DW1, const float* __restrict__ Db1,
    const float* __restrict__ Dw2, const float* __restrict__ Db2,
    float* __restrict__ out_alpha, float* __restrict__ out_eta) {
    __shared__ float sx[8][768];
    __shared__ float swF[32][65];
    __shared__ float swD[32][65];
    __shared__ float sred[2][8][32];
    __shared__ float spart[2][8];
    const int s = blockIdx.x;
    const int tid = threadIdx.x;
    const int b = tid >> 5;
    const int g = tid & 31;

    for (int i = tid; i < 6144; i += 256) {
        int bb = i / 768, e = i - bb * 768;
        sx[bb][e] = x[((size_t)bb * 1024 + s) * 768 + e];
    }
    float aF = 0.f, aD = 0.f;
    for (int k0 = 0; k0 < 768; k0 += 64) {
        __syncthreads();
        for (int i = tid; i < 2048; i += 256) {
            int rr = i >> 6, cc = i & 63;
            swF[rr][cc] = FW1[rr * 768 + k0 + cc];
            swD[rr][cc] = DW1[rr * 768 + k0 + cc];
        }
        __syncthreads();
#pragma unroll 8
        for (int kk = 0; kk < 64; kk++) {
            float xv = sx[b][k0 + kk];
            aF += swF[g][kk] * xv;
            aD += swD[g][kk] * xv;
        }
    }
    aF += Fb1[g];
    aD += Db1[g];
    float hF = aF / (1.f + expf(-aF));
    float hD = aD / (1.f + expf(-aD));
    sred[0][b][g] = Fw2[g] * hF;
    sred[1][b][g] = Dw2[g] * hD;
    __syncthreads();
    if (tid < 16) {
        int which = tid >> 3, bb = tid & 7;
        float acc = which ? Db2[0] : Fb2[0];
#pragma unroll
        for (int gg = 0; gg < 32; gg++) acc += sred[which][bb][gg];
        spart[which][bb] = 1.f / (1.f + expf(-acc));
    }
    __syncthreads();
    if (tid == 0) {
        float m = 0.f;
#pragma unroll
        for (int bb = 0; bb < 8; bb++) m += spart[0][bb];
        out_alpha[s] = m * 0.125f;
    }
    if (tid == 1) {
        float m = 0.f;
#pragma unroll
        for (int bb = 0; bb < 8; bb++) m += spart[1][bb];
        out_eta[s] = m * 0.125f;
    }
}

// ------------------------- the sequential scan -------------------------
// 128 CTAs * 384 threads. Each CTA owns 6 rows of W1,S1,W2,S2 and 6 cols of W2 (W2T,S2T).
// Dot phases: split-k over 12 warps (64 k each); lane = (b=l>>2, ks=l&3), 16 k per lane.
#define SCAN_SMEM_FLOATS (6 * 4608 + 3 * 6912 + 12 * 48 + 4 * 48 + 24)

__global__ __launch_bounds__(SCAN_T, 1) void scan_kernel(const float* __restrict__ MW1,
                                                         const float* __restrict__ Mb1,
                                                         const float* __restrict__ MW2,
                                                         const float* __restrict__ Mb2) {
    extern __shared__ float sm[];
    float* sW1  = sm;
    float* sS1  = sW1 + 4608;
    float* sW2  = sS1 + 4608;
    float* sS2  = sW2 + 4608;
    float* sW2T = sS2 + 4608;
    float* sS2T = sW2T + 4608;
    float* skt  = sS2T + 4608;  // [768][9]
    float* sh1  = skt + 6912;   // [768][9]
    float* sdy  = sh1 + 6912;   // [768][9]
    float* sred = sdy + 6912;   // [12][48]
    float* svt  = sred + 576;   // [6][8]
    float* sa1  = svt + 48;     // [6][8]
    float* sda  = sa1 + 48;     // [6][8]
    float* sdys = sda + 48;     // [6][8]
    float* sb1  = sdys + 48;    // [6]
    float* sSb1 = sb1 + 6;
    float* sb2  = sSb1 + 6;
    float* sSb2 = sb2 + 6;

    const int tid = threadIdx.x;
    const int c = blockIdx.x;
    const int r0 = c * RPC;
    const int w = tid >> 5;
    const int l = tid & 31;
    const int bb = l >> 2;
    const int ks = l & 3;
    const int kbase = w * 64 + ks * 16;

    // init state
    for (int i = tid; i < 4608; i += SCAN_T) {
        int rj = i / 768, d = i - rj * 768;
        sW1[i] = MW1[(r0 + rj) * 768 + d];
        sW2[i] = MW2[(r0 + rj) * 768 + d];
        sW2T[i] = MW2[d * 768 + r0 + rj];
        sS1[i] = 0.f;
        sS2[i] = 0.f;
        sS2T[i] = 0.f;
    }
    if (tid < 6) {
        sb1[tid] = Mb1[r0 + tid];
        sb2[tid] = Mb2[r0 + tid];
        sSb1[tid] = 0.f;
        sSb2[tid] = 0.f;
    }
    __syncthreads();

    for (int t = 0; t < Ss; t++) {
        const float at = g_alpha[t];
        const float et = g_eta[t];
        const float ia = 1.f - at;
        const int par = t & 1;

        // stage kt transposed [e][b] + vt slice
        {
            const float* kt = g_k + t * 6144;
            for (int i = tid; i < 6144; i += SCAN_T) {
                int b2 = i / 768, e = i - b2 * 768;
                skt[e * 9 + b2] = kt[i];
            }
            if (tid < 48) {
                int rj = tid >> 3, b2 = tid & 7;
                svt[tid] = g_v[t * 6144 + b2 * 768 + r0 + rj];
            }
        }
        __syncthreads();

        // ---- P1: a1/h1 for owned rows (split-k) ----
        {
            float kv[16];
#pragma unroll
            for (int kk = 0; kk < 16; kk++) kv[kk] = skt[(kbase + kk) * 9 + bb];
            float acc[6] = {0.f, 0.f, 0.f, 0.f, 0.f, 0.f};
#pragma unroll
            for (int kk4 = 0; kk4 < 4; kk4++) {
#pragma unroll
                for (int r = 0; r < 6; r++) {
                    float4 wv = *(const float4*)&sW1[r * 768 + kbase + 4 * kk4];
                    acc[r] = fmaf(wv.x, kv[4 * kk4 + 0], acc[r]);
                    acc[r] = fmaf(wv.y, kv[4 * kk4 + 1], acc[r]);
                    acc[r] = fmaf(wv.z, kv[4 * kk4 + 2], acc[r]);
                    acc[r] = fmaf(wv.w, kv[4 * kk4 + 3], acc[r]);
                }
            }
#pragma unroll
            for (int r = 0; r < 6; r++) {
                acc[r] += __shfl_xor_sync(0xffffffffu, acc[r], 1);
                acc[r] += __shfl_xor_sync(0xffffffffu, acc[r], 2);
            }
            if (ks == 0) {
#pragma unroll
                for (int r = 0; r < 6; r++) sred[w * 48 + r * 8 + bb] = acc[r];
            }
        }
        __syncthreads();
        if (tid < 48) {
            int r = tid >> 3, b2 = tid & 7;
            float s = 0.f;
#pragma unroll
            for (int ww = 0; ww < 12; ww++) s += sred[ww * 48 + tid];
            float a1 = s + sb1[r];
            sa1[tid] = a1;
            g_h1x[par][(r0 + r) * 8 + b2] = a1 / (1.f + expf(-a1));
        }
        grid_barrier();

        // ---- P2: y/dy for owned rows ----
        for (int i = tid; i < 6144; i += SCAN_T) {
            int e = i >> 3, b2 = i & 7;
            sh1[e * 9 + b2] = __ldcg(&g_h1x[par][i]);
        }
        __syncthreads();
        {
            float hv[16];
#pragma unroll
            for (int kk = 0; kk < 16; kk++) hv[kk] = sh1[(kbase + kk) * 9 + bb];
            float acc[6] = {0.f, 0.f, 0.f, 0.f, 0.f, 0.f};
#pragma unroll
            for (int kk4 = 0; kk4 < 4; kk4++) {
#pragma unroll
                for (int r = 0; r < 6; r++) {
                    float4 wv = *(const float4*)&sW2[r * 768 + kbase + 4 * kk4];
                    acc[r] = fmaf(wv.x, hv[4 * kk4 + 0], acc[r]);
                    acc[r] = fmaf(wv.y, hv[4 * kk4 + 1], acc[r]);
                    acc[r] = fmaf(wv.z, hv[4 * kk4 + 2], acc[r]);
                    acc[r] = fmaf(wv.w, hv[4 * kk4 + 3], acc[r]);
                }
            }
#pragma unroll
            for (int r = 0; r < 6; r++) {
                acc[r] += __shfl_xor_sync(0xffffffffu, acc[r], 1);
                acc[r] += __shfl_xor_sync(0xffffffffu, acc[r], 2);
            }
            if (ks == 0) {
#pragma unroll
                for (int r = 0; r < 6; r++) sred[w * 48 + r * 8 + bb] = acc[r];
            }
        }
        __syncthreads();
        if (tid < 48) {
            int r = tid >> 3, b2 = tid & 7;
            float s = 0.f;
#pragma unroll
            for (int ww = 0; ww < 12; ww++) s += sred[ww * 48 + tid];
            float dy = (s + sb2[r] - svt[tid]) * (2.f / 6144.f);
            sdys[tid] = dy;
            g_dyx[par][(r0 + r) * 8 + b2] = dy;
        }
        __syncthreads();
        if (tid < 6) {  // b2 update
            float gs = 0.f;
#pragma unroll
            for (int b2 = 0; b2 < 8; b2++) gs += sdys[tid * 8 + b2];
            float s2 = et * sSb2[tid] - THETA * gs;
            sSb2[tid] = s2;
            sb2[tid] = ia * sb2[tid] + s2;
        }
        grid_barrier();

        // ---- P3: dh1/da1 + all state updates ----
        for (int i = tid; i < 6144; i += SCAN_T) {
            int e = i >> 3, b2 = i & 7;
            sdy[e * 9 + b2] = __ldcg(&g_dyx[par][i]);
        }
        __syncthreads();
        {
            float dv[16];
#pragma unroll
            for (int kk = 0; kk < 16; kk++) dv[kk] = sdy[(kbase + kk) * 9 + bb];
            float acc[6] = {0.f, 0.f, 0.f, 0.f, 0.f, 0.f};
#pragma unroll
            for (int kk4 = 0; kk4 < 4; kk4++) {
#pragma unroll
                for (int r = 0; r < 6; r++) {
                    float4 wv = *(const float4*)&sW2T[r * 768 + kbase + 4 * kk4];
                    acc[r] = fmaf(wv.x, dv[4 * kk4 + 0], acc[r]);
                    acc[r] = fmaf(wv.y, dv[4 * kk4 + 1], acc[r]);
                    acc[r] = fmaf(wv.z, dv[4 * kk4 + 2], acc[r]);
                    acc[r] = fmaf(wv.w, dv[4 * kk4 + 3], acc[r]);
                }
            }
#pragma unroll
            for (int r = 0; r < 6; r++) {
                acc[r] += __shfl_xor_sync(0xffffffffu, acc[r], 1);
                acc[r] += __shfl_xor_sync(0xffffffffu, acc[r], 2);
            }
            if (ks == 0) {
#pragma unroll
                for (int r = 0; r < 6; r++) sred[w * 48 + r * 8 + bb] = acc[r];
            }
        }
        __syncthreads();
        if (tid < 48) {
            int r = tid >> 3;
            float s = 0.f;
#pragma unroll
            for (int ww = 0; ww < 12; ww++) s += sred[ww * 48 + tid];
            float a1 = sa1[tid];
            float sg = 1.f / (1.f + expf(-a1));
            float ds = sg * (1.f + a1 * (1.f - sg));
            (void)r;
            sda[tid] = s * ds;
        }
        __syncthreads();
        if (tid < 6) {  // b1 update
            float gs = 0.f;
#pragma unroll
            for (int b2 = 0; b2 < 8; b2++) gs += sda[tid * 8 + b2];
            float s1 = et * sSb1[tid] - THETA * gs;
            sSb1[tid] = s1;
            sb1[tid] = ia * sb1[tid] + s1;
        }

        // W1/S1 update: g[r,d] = sum_b da1[r,b]*kt[d,b]
        {
            float cA[48];
#pragma unroll
            for (int q = 0; q < 48; q++) cA[q] = sda[q];
#pragma unroll
            for (int it = 0; it < 2; it++) {
                int d = tid + it * SCAN_T;
                float kv8[8];
#pragma unroll
                for (int b2 = 0; b2 < 8; b2++) kv8[b2] = skt[d * 9 + b2];
#pragma unroll
                for (int r = 0; r < 6; r++) {
                    float gr = 0.f;
#pragma unroll
                    for (int b2 = 0; b2 < 8; b2++) gr = fmaf(cA[r * 8 + b2], kv8[b2], gr);
                    int idx = r * 768 + d;
                    float sv = fmaf(et, sS1[idx], -THETA * gr);
                    sS1[idx] = sv;
                    sW1[idx] = fmaf(ia, sW1[idx], sv);
                }
            }
        }
        // W2/S2 update: g[r,d] = sum_b dy[r,b]*h1[d,b]
        {
            float cB[48];
#pragma unroll
            for (int q = 0; q < 48; q++) cB[q] = sdys[q];
#pragma unroll
            for (int it = 0; it < 2; it++) {
                int d = tid + it * SCAN_T;
                float hv8[8];
#pragma unroll
                for (int b2 = 0; b2 < 8; b2++) hv8[b2] = sh1[d * 9 + b2];
#pragma unroll
                for (int r = 0; r < 6; r++) {
                    float gr = 0.f;
#pragma unroll
                    for (int b2 = 0; b2 < 8; b2++) gr = fmaf(cB[r * 8 + b2], hv8[b2], gr);
                    int idx = r * 768 + d;
                    float sv = fmaf(et, sS2[idx], -THETA * gr);
                    sS2[idx] = sv;
                    sW2[idx] = fmaf(ia, sW2[idx], sv);
                }
            }
        }
        // W2T/S2T update: g[dj,e] = sum_b dy[e,b]*h1[r0+dj,b]
        {
            float cT[48];
#pragma unroll
            for (int dj = 0; dj < 6; dj++)
#pragma unroll
                for (int b2 = 0; b2 < 8; b2++) cT[dj * 8 + b2] = sh1[(r0 + dj) * 9 + b2];
#pragma unroll
            for (int it = 0; it < 2; it++) {
                int e = tid + it * SCAN_T;
                float dv8[8];
#pragma unroll
                for (int b2 = 0; b2 < 8; b2++) dv8[b2] = sdy[e * 9 + b2];
#pragma unroll
                for (int dj = 0; dj < 6; dj++) {
                    float gr = 0.f;
#pragma unroll
                    for (int b2 = 0; b2 < 8; b2++) gr = fmaf(cT[dj * 8 + b2], dv8[b2], gr);
                    int idx = dj * 768 + e;
                    float sv = fmaf(et, sS2T[idx], -THETA * gr);
                    sS2T[idx] = sv;
                    sW2T[idx] = fmaf(ia, sW2T[idx], sv);
                }
            }
        }
        __syncthreads();
    }

    // write final state
    for (int i = tid; i < 4608; i += SCAN_T) {
        int rj = i / 768, d = i - rj * 768;
        g_W1f[(r0 + rj) * 768 + d] = sW1[i];
        g_W2f[(r0 + rj) * 768 + d] = sW2[i];
    }
    if (tid < 6) {
        g_b1f[r0 + tid] = sb1[tid];
        g_b2f[r0 + tid] = sb2[tid];
    }
}

// ------------------------- launch -------------------------
extern "C" void kernel_launch(void* const* d_in, const int* in_sizes, int n_in,
                              void* d_out, int out_size) {
    const float* x   = (const float*)d_in[0];
    const float* WKw = (const float*)d_in[1];
    const float* WKb = (const float*)d_in[2];
    const float* WVw = (const float*)d_in[3];
    const float* WVb = (const float*)d_in[4];
    const float* WQw = (const float*)d_in[5];
    const float* WQb = (const float*)d_in[6];
    const float* MW1 = (const float*)d_in[7];
    const float* Mb1 = (const float*)d_in[8];
    const float* MW2 = (const float*)d_in[9];
    const float* Mb2 = (const float*)d_in[10];
    const float* FW1 = (const float*)d_in[11];
    const float* Fb1 = (const float*)d_in[12];
    const float* Fw2 = (const float*)d_in[13];
    const float* Fb2 = (const float*)d_in[14];
    const float* DW1 = (const float*)d_in[15];
    const float* Db1 = (const float*)d_in[16];
    const float* Dw2 = (const float*)d_in[17];
    const float* Db2 = (const float*)d_in[18];
    float* out = (float*)d_out;

    float *p_k, *p_v, *p_q, *p_hid, *p_alpha, *p_eta, *p_W1f, *p_W2f, *p_b1f, *p_b2f;
    cudaGetSymbolAddress((void**)&p_k, g_k);
    cudaGetSymbolAddress((void**)&p_v, g_v);
    cudaGetSymbolAddress((void**)&p_q, g_q);
    cudaGetSymbolAddress((void**)&p_hid, g_hid);
    cudaGetSymbolAddress((void**)&p_alpha, g_alpha);
    cudaGetSymbolAddress((void**)&p_eta, g_eta);
    cudaGetSymbolAddress((void**)&p_W1f, g_W1f);
    cudaGetSymbolAddress((void**)&p_W2f, g_W2f);
    cudaGetSymbolAddress((void**)&p_b1f, g_b1f);
    cudaGetSymbolAddress((void**)&p_b2f, g_b2f);

    cudaFuncSetAttribute(scan_kernel, cudaFuncAttributeMaxDynamicSharedMemorySize,
                         SCAN_SMEM_FLOATS * 4);

    dim3 gg(128, 12);
    gemm_kernel<0, 1><<<gg, 256>>>(x, WKw, WKb, p_k);
    gemm_kernel<0, 1><<<gg, 256>>>(x, WVw, WVb, p_v);
    gemm_kernel<0, 0><<<gg, 256>>>(x, WQw, WQb, p_q);
    gates_kernel<<<Ss, 256>>>(x, FW1, Fb1, Fw2, Fb2, DW1, Db1, Dw2, Db2, p_alpha, p_eta);
    scan_kernel<<<NCTA, SCAN_T, SCAN_SMEM_FLOATS * 4>>>(MW1, Mb1, MW2, Mb2);
    gemm_kernel<1, 0><<<gg, 256>>>(p_q, p_W1f, p_b1f, p_hid);
    gemm_kernel<0, 0><<<gg, 256>>>(p_hid, p_W2f, p_b2f, out);
}